// round 1
// baseline (speedup 1.0000x reference)
#include <cuda_runtime.h>
#include <math.h>

#define LFRAMES 256
#define IMH 224
#define IMW 224
#define IMC 3
#define NOISE_LEN 766   // 3*L - 2
#define WIN 511         // 2*L - 1

// Per-frame 3x3 source-coordinate matrices (row-major), produced by kernel 1.
__device__ float g_M[LFRAMES * 9];

// ---------------------------------------------------------------------------
// Kernel 1: smoothing + matrix build. One block per output frame t (256 blocks,
// 128 threads). Window weights + normalization + matrix algebra in double
// (negligible fp64 volume, spread over all SMs); the 511-tap dot products in
// float via shfl/smem tree reduction.
// ---------------------------------------------------------------------------
__global__ void __launch_bounds__(128)
smooth_matrices_kernel(const float* __restrict__ noise,
                       const float* __restrict__ basis) {
    __shared__ float wn[WIN];          // normalized window (float)
    __shared__ double wsum_sh;
    __shared__ float red[4][4];        // [warp][row] partial sums
    __shared__ double wraw[WIN];       // raw double window (for exact sum)

    const int tid = threadIdx.x;
    const int t = blockIdx.x;          // frame index 0..255

    // Build raw window in double: w[j] = 1.1^j for j<255, 1.1^(510-j) for j>=255.
    for (int j = tid; j < WIN; j += 128) {
        int e = (j < 255) ? j : (510 - j);
        wraw[j] = pow(1.1, (double)e);
    }
    __syncthreads();
    if (tid == 0) {
        double s = 0.0;
        for (int j = 0; j < WIN; j++) s += wraw[j];
        wsum_sh = s;
    }
    __syncthreads();
    const double inv = 1.0 / wsum_sh;
    for (int j = tid; j < WIN; j += 128) {
        wn[j] = (float)(wraw[j] * inv);
    }
    __syncthreads();

    // 4 dot products of length 511 (valid convolution at offset t).
    float part[4] = {0.f, 0.f, 0.f, 0.f};
    for (int r = 0; r < 4; r++) {
        const float* nr = noise + r * NOISE_LEN + t;
        float acc = 0.f;
        for (int k = tid; k < WIN; k += 128) {
            acc = fmaf(nr[k], wn[k], acc);
        }
        part[r] = acc;
    }
    // warp reduce
    const int lane = tid & 31;
    const int wrp = tid >> 5;
    for (int r = 0; r < 4; r++) {
        float v = part[r];
        #pragma unroll
        for (int off = 16; off > 0; off >>= 1)
            v += __shfl_down_sync(0xFFFFFFFFu, v, off);
        if (lane == 0) red[wrp][r] = v;
    }
    __syncthreads();

    if (tid == 0) {
        double wv[4];
        double sum_wv = 0.0;
        for (int r = 0; r < 4; r++) {
            float v = red[0][r] + red[1][r] + red[2][r] + red[3][r];
            double d = (double)v;
            if (d < 0.0) d = 0.0;       // relu on smoothed value
            wv[r] = d;
            sum_wv += d;
        }
        // warp = sum_r wv_r * basis_r + (4 - sum wv) * I
        double W9[9];
        const double rem = 4.0 - sum_wv;
        for (int i = 0; i < 9; i++) {
            double e = 0.0;
            for (int r = 0; r < 4; r++)
                e += wv[r] * (double)basis[r * 9 + i];
            if (i == 0 || i == 4 || i == 8) e += rem;
            W9[i] = e;
        }
        // M = A * W * B, A = [[223,0,111.5],[0,223,111.5],[0,0,1]],
        //                B = [[1/223,0,-0.5],[0,1/223,-0.5],[0,0,1]]
        const double s = 1.0 / 223.0;
        double T[9];
        for (int i = 0; i < 3; i++) {
            T[i * 3 + 0] = W9[i * 3 + 0] * s;
            T[i * 3 + 1] = W9[i * 3 + 1] * s;
            T[i * 3 + 2] = -0.5 * W9[i * 3 + 0] - 0.5 * W9[i * 3 + 1] + W9[i * 3 + 2];
        }
        double Mm[9];
        for (int j = 0; j < 3; j++) {
            Mm[0 * 3 + j] = 223.0 * T[0 * 3 + j] + 111.5 * T[2 * 3 + j];
            Mm[1 * 3 + j] = 223.0 * T[1 * 3 + j] + 111.5 * T[2 * 3 + j];
            Mm[2 * 3 + j] = T[2 * 3 + j];
        }
        for (int i = 0; i < 9; i++)
            g_M[t * 9 + i] = (float)Mm[i];
    }
}

// ---------------------------------------------------------------------------
// Kernel 2: projective bilinear warp. One thread per output pixel.
// grid = (224 rows, 256 frames), block = 224 threads (x).
// ---------------------------------------------------------------------------
__global__ void __launch_bounds__(224)
warp_kernel(const float* __restrict__ x, float* __restrict__ out) {
    const int px = threadIdx.x;     // 0..223
    const int py = blockIdx.x;      // 0..223
    const int l  = blockIdx.y;      // 0..255

    const float* M = g_M + l * 9;
    const float fx = (float)px, fy = (float)py;

    const float den = M[6] * fx + M[7] * fy + M[8];
    const float sx = (M[0] * fx + M[1] * fy + M[2]) / den;
    const float sy = (M[3] * fx + M[4] * fy + M[5]) / den;

    const float x0f = floorf(sx);
    const float y0f = floorf(sy);
    const float wx = sx - x0f;
    const float wy = sy - y0f;

    const float* img = x + (size_t)l * (IMH * IMW * IMC);

    float acc0 = 0.f, acc1 = 0.f, acc2 = 0.f;
    #pragma unroll
    for (int dy = 0; dy < 2; dy++) {
        #pragma unroll
        for (int dx = 0; dx < 2; dx++) {
            const float xf = x0f + (float)dx;
            const float yf = y0f + (float)dy;
            const bool valid = (xf >= 0.f) && (xf <= (float)(IMW - 1)) &&
                               (yf >= 0.f) && (yf <= (float)(IMH - 1));
            const int xi = (int)fminf(fmaxf(xf, 0.f), (float)(IMW - 1));
            const int yi = (int)fminf(fmaxf(yf, 0.f), (float)(IMH - 1));
            const float wgt = (dy ? wy : (1.f - wy)) * (dx ? wx : (1.f - wx));
            const float m = valid ? wgt : 0.f;
            const float* p = img + (yi * IMW + xi) * IMC;
            acc0 = fmaf(p[0], m, acc0);
            acc1 = fmaf(p[1], m, acc1);
            acc2 = fmaf(p[2], m, acc2);
        }
    }

    float* o = out + ((size_t)(l * IMH + py) * IMW + px) * IMC;
    o[0] = acc0;
    o[1] = acc1;
    o[2] = acc2;
}

extern "C" void kernel_launch(void* const* d_in, const int* in_sizes, int n_in,
                              void* d_out, int out_size) {
    const float* x     = (const float*)d_in[0];   // (8,32,224,224,3)
    const float* noise = (const float*)d_in[1];   // (4, 766)
    const float* basis = (const float*)d_in[2];   // (4, 3, 3)
    float* out = (float*)d_out;

    smooth_matrices_kernel<<<LFRAMES, 128>>>(noise, basis);
    warp_kernel<<<dim3(IMH, LFRAMES), IMW>>>(x, out);
}

// round 2
// speedup vs baseline: 1.0841x; 1.0841x over previous
#include <cuda_runtime.h>
#include <math.h>

#define LFRAMES 256
#define IMH 224
#define IMW 224
#define IMC 3
#define NOISE_LEN 766   // 3*L - 2
#define WIN 511         // 2*L - 1

// Per-frame 3x3 source-coordinate matrices (row-major), produced by kernel 1.
__device__ float g_M[LFRAMES * 9];

// ---------------------------------------------------------------------------
// Kernel 1: smoothing + matrix build. One block per output frame t (256 blocks,
// 128 threads). Window normalization via closed-form geometric sum (no serial
// 511-element reduction); dot products parallel float; matrix algebra float.
// ---------------------------------------------------------------------------
__global__ void __launch_bounds__(128)
smooth_matrices_kernel(const float* __restrict__ noise,
                       const float* __restrict__ basis) {
    __shared__ float wn[WIN];          // normalized window (float)
    __shared__ float red[4][4];        // [warp][row] partial sums

    const int tid = threadIdx.x;
    const int t = blockIdx.x;          // frame index 0..255

    // Closed-form window sum: w = [1.1^0..1.1^254] ++ [1.1^255..1.1^0]
    // sum = (1.1^255 - 1)/0.1 + (1.1^256 - 1)/0.1
    const double p255 = pow(1.1, 255.0);
    const double wsum = (p255 - 1.0) / 0.1 + (p255 * 1.1 - 1.0) / 0.1;
    const double inv = 1.0 / wsum;

    for (int j = tid; j < WIN; j += 128) {
        int e = (j < 255) ? j : (510 - j);
        wn[j] = (float)(pow(1.1, (double)e) * inv);
    }
    __syncthreads();

    // 4 dot products of length 511 (valid convolution at offset t).
    float part[4] = {0.f, 0.f, 0.f, 0.f};
    #pragma unroll
    for (int r = 0; r < 4; r++) {
        const float* nr = noise + r * NOISE_LEN + t;
        float acc = 0.f;
        for (int k = tid; k < WIN; k += 128) {
            acc = fmaf(__ldg(nr + k), wn[k], acc);
        }
        part[r] = acc;
    }
    // warp reduce
    const int lane = tid & 31;
    const int wrp = tid >> 5;
    #pragma unroll
    for (int r = 0; r < 4; r++) {
        float v = part[r];
        #pragma unroll
        for (int off = 16; off > 0; off >>= 1)
            v += __shfl_down_sync(0xFFFFFFFFu, v, off);
        if (lane == 0) red[wrp][r] = v;
    }
    __syncthreads();

    if (tid == 0) {
        float wv[4];
        float sum_wv = 0.f;
        #pragma unroll
        for (int r = 0; r < 4; r++) {
            float v = (red[0][r] + red[1][r]) + (red[2][r] + red[3][r]);
            v = fmaxf(v, 0.f);          // relu on smoothed value
            wv[r] = v;
            sum_wv += v;
        }
        // warp = sum_r wv_r * basis_r + (4 - sum wv) * I
        float W9[9];
        const float rem = 4.f - sum_wv;
        #pragma unroll
        for (int i = 0; i < 9; i++) {
            float e = 0.f;
            #pragma unroll
            for (int r = 0; r < 4; r++)
                e = fmaf(wv[r], __ldg(basis + r * 9 + i), e);
            if (i == 0 || i == 4 || i == 8) e += rem;
            W9[i] = e;
        }
        // M = A * W * B, A = [[223,0,111.5],[0,223,111.5],[0,0,1]],
        //                B = [[1/223,0,-0.5],[0,1/223,-0.5],[0,0,1]]
        const float s = 1.f / 223.f;
        float T[9];
        #pragma unroll
        for (int i = 0; i < 3; i++) {
            T[i * 3 + 0] = W9[i * 3 + 0] * s;
            T[i * 3 + 1] = W9[i * 3 + 1] * s;
            T[i * 3 + 2] = -0.5f * W9[i * 3 + 0] - 0.5f * W9[i * 3 + 1] + W9[i * 3 + 2];
        }
        float Mm[9];
        #pragma unroll
        for (int j = 0; j < 3; j++) {
            Mm[0 * 3 + j] = 223.f * T[0 * 3 + j] + 111.5f * T[2 * 3 + j];
            Mm[1 * 3 + j] = 223.f * T[1 * 3 + j] + 111.5f * T[2 * 3 + j];
            Mm[2 * 3 + j] = T[2 * 3 + j];
        }
        #pragma unroll
        for (int i = 0; i < 9; i++)
            g_M[t * 9 + i] = Mm[i];
    }
}

// ---------------------------------------------------------------------------
// Branchless 3-channel fetch: pixel idx -> floats at q=3*idx..3*idx+2.
// If idx even: float2 @ q (8B aligned) + float @ q+2.
// If idx odd:  float  @ q + float2 @ q+1 (8B aligned).
// 2 loads instead of 3; assembled with SELs.
// ---------------------------------------------------------------------------
__device__ __forceinline__ float3 fetch3(const float* __restrict__ img, int idx) {
    const int q = idx * 3;
    const int odd = idx & 1;
    const float* base = img + q;
    float  sc = __ldg(base + (odd ? 0 : 2));
    float2 v  = __ldg((const float2*)(base + odd));
    float3 r;
    r.x = odd ? sc  : v.x;
    r.y = odd ? v.x : v.y;
    r.z = odd ? v.y : sc;
    return r;
}

// ---------------------------------------------------------------------------
// Kernel 2: projective bilinear warp. 4 consecutive pixels per thread,
// 3x STG.128 output per thread. block (56,4) = 224 thr, grid (56, 256).
// ---------------------------------------------------------------------------
__global__ void __launch_bounds__(224)
warp_kernel(const float* __restrict__ x, float* __restrict__ out) {
    const int px0 = threadIdx.x * 4;                 // 0..220
    const int py  = blockIdx.x * 4 + threadIdx.y;    // 0..223
    const int l   = blockIdx.y;                      // 0..255

    const float* Mg = g_M + l * 9;
    float M0 = __ldg(Mg + 0), M1 = __ldg(Mg + 1), M2 = __ldg(Mg + 2);
    float M3 = __ldg(Mg + 3), M4 = __ldg(Mg + 4), M5 = __ldg(Mg + 5);
    float M6 = __ldg(Mg + 6), M7 = __ldg(Mg + 7), M8 = __ldg(Mg + 8);

    const float fy = (float)py;
    const float* img = x + (size_t)l * (IMH * IMW * IMC);

    float res[12];

    #pragma unroll
    for (int i = 0; i < 4; i++) {
        const float fx = (float)(px0 + i);
        const float den = fmaf(M6, fx, fmaf(M7, fy, M8));
        const float rden = __frcp_rn(den);
        const float sx = fmaf(M0, fx, fmaf(M1, fy, M2)) * rden;
        const float sy = fmaf(M3, fx, fmaf(M4, fy, M5)) * rden;

        const float x0f = floorf(sx);
        const float y0f = floorf(sy);
        const float wx = sx - x0f;
        const float wy = sy - y0f;

        float a0 = 0.f, a1 = 0.f, a2 = 0.f;
        #pragma unroll
        for (int dy = 0; dy < 2; dy++) {
            #pragma unroll
            for (int dx = 0; dx < 2; dx++) {
                const float xf = x0f + (float)dx;
                const float yf = y0f + (float)dy;
                const bool valid = (xf >= 0.f) && (xf <= (float)(IMW - 1)) &&
                                   (yf >= 0.f) && (yf <= (float)(IMH - 1));
                const int xi = (int)fminf(fmaxf(xf, 0.f), (float)(IMW - 1));
                const int yi = (int)fminf(fmaxf(yf, 0.f), (float)(IMH - 1));
                const float wgt = (dy ? wy : (1.f - wy)) * (dx ? wx : (1.f - wx));
                const float m = valid ? wgt : 0.f;
                const float3 p = fetch3(img, yi * IMW + xi);
                a0 = fmaf(p.x, m, a0);
                a1 = fmaf(p.y, m, a1);
                a2 = fmaf(p.z, m, a2);
            }
        }
        res[i * 3 + 0] = a0;
        res[i * 3 + 1] = a1;
        res[i * 3 + 2] = a2;
    }

    // 4 pixels * 3 channels = 12 floats = 48 bytes, 16B-aligned (px0 % 4 == 0).
    float4* o = (float4*)(out + ((size_t)(l * IMH + py) * IMW + px0) * IMC);
    o[0] = make_float4(res[0], res[1], res[2],  res[3]);
    o[1] = make_float4(res[4], res[5], res[6],  res[7]);
    o[2] = make_float4(res[8], res[9], res[10], res[11]);
}

extern "C" void kernel_launch(void* const* d_in, const int* in_sizes, int n_in,
                              void* d_out, int out_size) {
    const float* x     = (const float*)d_in[0];   // (8,32,224,224,3)
    const float* noise = (const float*)d_in[1];   // (4, 766)
    const float* basis = (const float*)d_in[2];   // (4, 3, 3)
    float* out = (float*)d_out;

    smooth_matrices_kernel<<<LFRAMES, 128>>>(noise, basis);
    warp_kernel<<<dim3(IMH / 4, LFRAMES), dim3(56, 4)>>>(x, out);
}

// round 3
// speedup vs baseline: 1.4590x; 1.3458x over previous
#include <cuda_runtime.h>
#include <math.h>

#define LFRAMES 256
#define IMH 224
#define IMW 224
#define IMC 3
#define NOISE_LEN 766   // 3*L - 2
#define WIN 511         // 2*L - 1
#define ROWF (IMW * IMC)  // 672 floats per image row

// Per-frame 3x3 source-coordinate matrices (row-major), produced by kernel 1.
__device__ float g_M[LFRAMES * 9];

// log2(1.1)
#define LOG2_BASE 0.13750352374993496

// ---------------------------------------------------------------------------
// Kernel 1: smoothing + matrix build. One block per output frame t (256 blocks,
// 128 threads). Window weights via double exp2 (cheap), normalization via
// closed-form geometric sum, dot products in parallel float, matrices float.
// ---------------------------------------------------------------------------
__global__ void __launch_bounds__(128)
smooth_matrices_kernel(const float* __restrict__ noise,
                       const float* __restrict__ basis) {
    __shared__ float wn[WIN];          // normalized window (float)
    __shared__ float red[4][4];        // [warp][row] partial sums

    const int tid = threadIdx.x;
    const int t = blockIdx.x;          // frame index 0..255

    // Closed-form window sum: w = [1.1^0..1.1^254] ++ [1.1^255..1.1^0]
    // sum = (1.1^255 - 1)/0.1 + (1.1^256 - 1)/0.1
    const double p255 = exp2(255.0 * LOG2_BASE);
    const double wsum = (p255 - 1.0) / 0.1 + (p255 * 1.1 - 1.0) / 0.1;
    const double inv = 1.0 / wsum;

    for (int j = tid; j < WIN; j += 128) {
        int e = (j < 255) ? j : (510 - j);
        wn[j] = (float)(exp2((double)e * LOG2_BASE) * inv);
    }
    __syncthreads();

    // 4 dot products of length 511 (valid convolution at offset t).
    float part[4] = {0.f, 0.f, 0.f, 0.f};
    #pragma unroll
    for (int r = 0; r < 4; r++) {
        const float* nr = noise + r * NOISE_LEN + t;
        float acc = 0.f;
        #pragma unroll 4
        for (int k = tid; k < WIN; k += 128) {
            acc = fmaf(__ldg(nr + k), wn[k], acc);
        }
        part[r] = acc;
    }
    // warp reduce
    const int lane = tid & 31;
    const int wrp = tid >> 5;
    #pragma unroll
    for (int r = 0; r < 4; r++) {
        float v = part[r];
        #pragma unroll
        for (int off = 16; off > 0; off >>= 1)
            v += __shfl_down_sync(0xFFFFFFFFu, v, off);
        if (lane == 0) red[wrp][r] = v;
    }
    __syncthreads();

    if (tid == 0) {
        float wv[4];
        float sum_wv = 0.f;
        #pragma unroll
        for (int r = 0; r < 4; r++) {
            float v = (red[0][r] + red[1][r]) + (red[2][r] + red[3][r]);
            v = fmaxf(v, 0.f);          // relu on smoothed value
            wv[r] = v;
            sum_wv += v;
        }
        // warp = sum_r wv_r * basis_r + (4 - sum wv) * I
        float W9[9];
        const float rem = 4.f - sum_wv;
        #pragma unroll
        for (int i = 0; i < 9; i++) {
            float e = 0.f;
            #pragma unroll
            for (int r = 0; r < 4; r++)
                e = fmaf(wv[r], __ldg(basis + r * 9 + i), e);
            if (i == 0 || i == 4 || i == 8) e += rem;
            W9[i] = e;
        }
        // M = A * W * B, A = [[223,0,111.5],[0,223,111.5],[0,0,1]],
        //                B = [[1/223,0,-0.5],[0,1/223,-0.5],[0,0,1]]
        const float s = 1.f / 223.f;
        float T[9];
        #pragma unroll
        for (int i = 0; i < 3; i++) {
            T[i * 3 + 0] = W9[i * 3 + 0] * s;
            T[i * 3 + 1] = W9[i * 3 + 1] * s;
            T[i * 3 + 2] = -0.5f * W9[i * 3 + 0] - 0.5f * W9[i * 3 + 1] + W9[i * 3 + 2];
        }
        float Mm[9];
        #pragma unroll
        for (int j = 0; j < 3; j++) {
            Mm[0 * 3 + j] = 223.f * T[0 * 3 + j] + 111.5f * T[2 * 3 + j];
            Mm[1 * 3 + j] = 223.f * T[1 * 3 + j] + 111.5f * T[2 * 3 + j];
            Mm[2 * 3 + j] = T[2 * 3 + j];
        }
        #pragma unroll
        for (int i = 0; i < 9; i++)
            g_M[t * 9 + i] = Mm[i];
    }
}

// ---------------------------------------------------------------------------
// Branchless 3-channel fetch from a row pointer: pixel xi -> 3 floats at
// q = 3*xi. Even xi: float2 @ q (8B aligned) + float @ q+2.
// Odd xi:  float @ q + float2 @ q+1 (8B aligned). 2 loads instead of 3.
// ---------------------------------------------------------------------------
__device__ __forceinline__ float3 fetch3(const float* __restrict__ row, int xi) {
    const int q = xi * 3;
    const int odd = xi & 1;
    const float* base = row + q;
    float  sc = __ldg(base + (odd ? 0 : 2));
    float2 v  = __ldg((const float2*)(base + odd));
    float3 r;
    r.x = odd ? sc  : v.x;
    r.y = odd ? v.x : v.y;
    r.z = odd ? v.y : sc;
    return r;
}

// ---------------------------------------------------------------------------
// Kernel 2: projective bilinear warp. One thread per output pixel, lanes =
// consecutive pixels (3-line LDG spans). grid (224, 256), block 224.
// ---------------------------------------------------------------------------
__global__ void __launch_bounds__(224)
warp_kernel(const float* __restrict__ x, float* __restrict__ out) {
    const int px = threadIdx.x;     // 0..223
    const int py = blockIdx.x;      // 0..223
    const int l  = blockIdx.y;      // 0..255

    const float* Mg = g_M + l * 9;
    const float M0 = __ldg(Mg + 0), M1 = __ldg(Mg + 1), M2 = __ldg(Mg + 2);
    const float M3 = __ldg(Mg + 3), M4 = __ldg(Mg + 4), M5 = __ldg(Mg + 5);
    const float M6 = __ldg(Mg + 6), M7 = __ldg(Mg + 7), M8 = __ldg(Mg + 8);

    const float fx = (float)px, fy = (float)py;

    const float den = fmaf(M6, fx, fmaf(M7, fy, M8));
    const float rden = __frcp_rn(den);
    const float sx = fmaf(M0, fx, fmaf(M1, fy, M2)) * rden;
    const float sy = fmaf(M3, fx, fmaf(M4, fy, M5)) * rden;

    const float x0f = floorf(sx);
    const float y0f = floorf(sy);
    const float wx = sx - x0f;
    const float wy = sy - y0f;
    const float x1f = x0f + 1.f;
    const float y1f = y0f + 1.f;

    // Per-corner validity + clamped integer coords (matches reference clip).
    const float W1 = (float)(IMW - 1), H1 = (float)(IMH - 1);
    const bool vx0 = (x0f >= 0.f) && (x0f <= W1);
    const bool vx1 = (x1f >= 0.f) && (x1f <= W1);
    const bool vy0 = (y0f >= 0.f) && (y0f <= H1);
    const bool vy1 = (y1f >= 0.f) && (y1f <= H1);
    const int xi0 = (int)fminf(fmaxf(x0f, 0.f), W1);
    const int xi1 = (int)fminf(fmaxf(x1f, 0.f), W1);
    const int yi0 = (int)fminf(fmaxf(y0f, 0.f), H1);
    const int yi1 = (int)fminf(fmaxf(y1f, 0.f), H1);

    const float w00 = (vy0 && vx0) ? (1.f - wy) * (1.f - wx) : 0.f;
    const float w01 = (vy0 && vx1) ? (1.f - wy) * wx         : 0.f;
    const float w10 = (vy1 && vx0) ? wy * (1.f - wx)         : 0.f;
    const float w11 = (vy1 && vx1) ? wy * wx                 : 0.f;

    const float* img  = x + (size_t)l * (IMH * ROWF);
    const float* row0 = img + yi0 * ROWF;
    const float* row1 = img + yi1 * ROWF;

    const float3 p00 = fetch3(row0, xi0);
    const float3 p01 = fetch3(row0, xi1);
    const float3 p10 = fetch3(row1, xi0);
    const float3 p11 = fetch3(row1, xi1);

    float a0 = p00.x * w00, a1 = p00.y * w00, a2 = p00.z * w00;
    a0 = fmaf(p01.x, w01, a0); a1 = fmaf(p01.y, w01, a1); a2 = fmaf(p01.z, w01, a2);
    a0 = fmaf(p10.x, w10, a0); a1 = fmaf(p10.y, w10, a1); a2 = fmaf(p10.z, w10, a2);
    a0 = fmaf(p11.x, w11, a0); a1 = fmaf(p11.y, w11, a1); a2 = fmaf(p11.z, w11, a2);

    float* o = out + (size_t)(l * IMH + py) * ROWF + px * 3;
    o[0] = a0;
    o[1] = a1;
    o[2] = a2;
}

extern "C" void kernel_launch(void* const* d_in, const int* in_sizes, int n_in,
                              void* d_out, int out_size) {
    const float* x     = (const float*)d_in[0];   // (8,32,224,224,3)
    const float* noise = (const float*)d_in[1];   // (4, 766)
    const float* basis = (const float*)d_in[2];   // (4, 3, 3)
    float* out = (float*)d_out;

    smooth_matrices_kernel<<<LFRAMES, 128>>>(noise, basis);
    warp_kernel<<<dim3(IMH, LFRAMES), IMW>>>(x, out);
}

// round 4
// speedup vs baseline: 1.5953x; 1.0934x over previous
#include <cuda_runtime.h>
#include <math.h>

#define LFRAMES 256
#define IMH 224
#define IMW 224
#define IMC 3
#define NOISE_LEN 766     // 3*L - 2
#define WIN 511           // 2*L - 1
#define ROWF (IMW * IMC)  // 672 floats per image row

// Per-frame 3x3 source-coordinate matrices (row-major), produced by kernel 1.
__device__ float g_M[LFRAMES * 9];

// log2(1.1)
#define LOG2_BASE 0.13750352374993496f

// ---------------------------------------------------------------------------
// Kernel 1: smoothing + matrix build. One block per output frame t (256 blocks,
// 128 threads). Window weights via exp2f (MUFU), normalization closed-form,
// dot products parallel float, matrix algebra float.
// ---------------------------------------------------------------------------
__global__ void __launch_bounds__(128)
smooth_matrices_kernel(const float* __restrict__ noise,
                       const float* __restrict__ basis) {
    __shared__ float wn[WIN];          // normalized window (float)
    __shared__ float red[4][4];        // [warp][row] partial sums

    const int tid = threadIdx.x;
    const int t = blockIdx.x;          // frame index 0..255

    // Closed-form window sum: w = [1.1^0..1.1^254] ++ [1.1^255..1.1^0]
    // sum = (1.1^255 - 1)/0.1 + (1.1^256 - 1)/0.1
    const float p255 = exp2f(255.f * LOG2_BASE);
    const float wsum = (p255 - 1.f) * 10.f + (p255 * 1.1f - 1.f) * 10.f;
    const float inv = 1.f / wsum;

    for (int j = tid; j < WIN; j += 128) {
        int e = (j < 255) ? j : (510 - j);
        wn[j] = exp2f((float)e * LOG2_BASE) * inv;
    }
    __syncthreads();

    // 4 dot products of length 511 (valid convolution at offset t).
    float part[4] = {0.f, 0.f, 0.f, 0.f};
    #pragma unroll
    for (int r = 0; r < 4; r++) {
        const float* nr = noise + r * NOISE_LEN + t;
        float acc = 0.f;
        #pragma unroll 4
        for (int k = tid; k < WIN; k += 128) {
            acc = fmaf(__ldg(nr + k), wn[k], acc);
        }
        part[r] = acc;
    }
    // warp reduce
    const int lane = tid & 31;
    const int wrp = tid >> 5;
    #pragma unroll
    for (int r = 0; r < 4; r++) {
        float v = part[r];
        #pragma unroll
        for (int off = 16; off > 0; off >>= 1)
            v += __shfl_down_sync(0xFFFFFFFFu, v, off);
        if (lane == 0) red[wrp][r] = v;
    }
    __syncthreads();

    if (tid == 0) {
        float wv[4];
        float sum_wv = 0.f;
        #pragma unroll
        for (int r = 0; r < 4; r++) {
            float v = (red[0][r] + red[1][r]) + (red[2][r] + red[3][r]);
            v = fmaxf(v, 0.f);          // relu on smoothed value
            wv[r] = v;
            sum_wv += v;
        }
        // warp = sum_r wv_r * basis_r + (4 - sum wv) * I
        float W9[9];
        const float rem = 4.f - sum_wv;
        #pragma unroll
        for (int i = 0; i < 9; i++) {
            float e = 0.f;
            #pragma unroll
            for (int r = 0; r < 4; r++)
                e = fmaf(wv[r], __ldg(basis + r * 9 + i), e);
            if (i == 0 || i == 4 || i == 8) e += rem;
            W9[i] = e;
        }
        // M = A * W * B, A = [[223,0,111.5],[0,223,111.5],[0,0,1]],
        //                B = [[1/223,0,-0.5],[0,1/223,-0.5],[0,0,1]]
        const float s = 1.f / 223.f;
        float T[9];
        #pragma unroll
        for (int i = 0; i < 3; i++) {
            T[i * 3 + 0] = W9[i * 3 + 0] * s;
            T[i * 3 + 1] = W9[i * 3 + 1] * s;
            T[i * 3 + 2] = -0.5f * W9[i * 3 + 0] - 0.5f * W9[i * 3 + 1] + W9[i * 3 + 2];
        }
        float Mm[9];
        #pragma unroll
        for (int j = 0; j < 3; j++) {
            Mm[0 * 3 + j] = 223.f * T[0 * 3 + j] + 111.5f * T[2 * 3 + j];
            Mm[1 * 3 + j] = 223.f * T[1 * 3 + j] + 111.5f * T[2 * 3 + j];
            Mm[2 * 3 + j] = T[2 * 3 + j];
        }
        #pragma unroll
        for (int i = 0; i < 9; i++)
            g_M[t * 9 + i] = Mm[i];
    }
}

// ---------------------------------------------------------------------------
// Extract the two 3-float corner pixels from a 9-float aligned window.
// vflat = [A.xyzw, B.xyzw, C]; span[i] = vflat[s+i] (s in 0..3);
// p0 = span[pos0? 3..5 : 0..2], p1 = span[pos1? 3..5 : 0..2].
// ---------------------------------------------------------------------------
__device__ __forceinline__ void extract2px(const float4 A, const float4 Bv, float C,
                                           bool t2, bool t1, bool pos0, bool pos1,
                                           float3& p0, float3& p1) {
    const float u0 = t2 ? A.z  : A.x;
    const float u1 = t2 ? A.w  : A.y;
    const float u2 = t2 ? Bv.x : A.z;
    const float u3 = t2 ? Bv.y : A.w;
    const float u4 = t2 ? Bv.z : Bv.x;
    const float u5 = t2 ? Bv.w : Bv.y;
    const float u6 = t2 ? C    : Bv.z;

    const float s0 = t1 ? u1 : u0;
    const float s1 = t1 ? u2 : u1;
    const float s2 = t1 ? u3 : u2;
    const float s3 = t1 ? u4 : u3;
    const float s4 = t1 ? u5 : u4;
    const float s5 = t1 ? u6 : u5;

    p0.x = pos0 ? s3 : s0;  p0.y = pos0 ? s4 : s1;  p0.z = pos0 ? s5 : s2;
    p1.x = pos1 ? s3 : s0;  p1.y = pos1 ? s4 : s1;  p1.z = pos1 ? s5 : s2;
}

// ---------------------------------------------------------------------------
// Kernel 2: projective bilinear warp. One thread per output pixel; per source
// row both x-corners come from one aligned float4-pair span (2 LDG.128 +
// rare LDG.32) with SEL extraction. grid (224, 256), block 224.
// ---------------------------------------------------------------------------
__global__ void __launch_bounds__(224)
warp_kernel(const float* __restrict__ x, float* __restrict__ out) {
    const int px = threadIdx.x;     // 0..223
    const int py = blockIdx.x;      // 0..223
    const int l  = blockIdx.y;      // 0..255

    const float* Mg = g_M + l * 9;
    const float M0 = __ldg(Mg + 0), M1 = __ldg(Mg + 1), M2 = __ldg(Mg + 2);
    const float M3 = __ldg(Mg + 3), M4 = __ldg(Mg + 4), M5 = __ldg(Mg + 5);
    const float M6 = __ldg(Mg + 6), M7 = __ldg(Mg + 7), M8 = __ldg(Mg + 8);

    const float fx = (float)px, fy = (float)py;

    const float den = fmaf(M6, fx, fmaf(M7, fy, M8));
    const float rden = __frcp_rn(den);
    const float sx = fmaf(M0, fx, fmaf(M1, fy, M2)) * rden;
    const float sy = fmaf(M3, fx, fmaf(M4, fy, M5)) * rden;

    const float x0f = floorf(sx);
    const float y0f = floorf(sy);
    const float wx = sx - x0f;
    const float wy = sy - y0f;

    const float W1 = (float)(IMW - 1), H1 = (float)(IMH - 1);

    // x-corner validity
    const bool vx0 = (x0f >= 0.f) && (x0f <= W1);
    const bool vx1 = (x0f >= -1.f) && (x0f <= W1 - 1.f);
    // y-corner validity + clamped rows
    const float y1f = y0f + 1.f;
    const bool vy0 = (y0f >= 0.f) && (y0f <= H1);
    const bool vy1 = (y1f >= 0.f) && (y1f <= H1);
    const int yi0 = (int)fminf(fmaxf(y0f, 0.f), H1);
    const int yi1 = (int)fminf(fmaxf(y1f, 0.f), H1);

    const float w00 = (vy0 && vx0) ? (1.f - wy) * (1.f - wx) : 0.f;
    const float w01 = (vy0 && vx1) ? (1.f - wy) * wx         : 0.f;
    const float w10 = (vy1 && vx0) ? wy * (1.f - wx)         : 0.f;
    const float w11 = (vy1 && vx1) ? wy * wx                 : 0.f;

    // x-span: base = clamp(x0, 0, 222); span covers pixels base, base+1.
    const float basef = fminf(fmaxf(x0f, 0.f), 222.f);
    const int base = (int)basef;
    const int fi = base * 3;          // float index of span start in row
    const int s  = fi & 3;            // shift within aligned float4 pair
    const int fa = fi & ~3;           // 16B-aligned float index
    const bool t2 = (s & 2) != 0;
    const bool t1 = (s & 1) != 0;
    const bool pos0 = (x0f > 222.5f); // xi0 == base+1 (right clamp)
    const bool pos1 = (x0f > -0.5f);  // xi1 == base+1 (normal); else left clamp

    const float* img  = x + (size_t)l * (IMH * ROWF);
    const float* row0 = img + yi0 * ROWF;
    const float* row1 = img + yi1 * ROWF;

    const float4 A0 = __ldg((const float4*)(row0 + fa));
    const float4 B0 = __ldg((const float4*)(row0 + fa + 4));
    const float4 A1 = __ldg((const float4*)(row1 + fa));
    const float4 B1 = __ldg((const float4*)(row1 + fa + 4));
    float C0 = 0.f, C1 = 0.f;
    if (s == 3) {                     // rare: span needs a 9th float
        C0 = __ldg(row0 + fa + 8);
        C1 = __ldg(row1 + fa + 8);
    }

    float3 p00, p01, p10, p11;
    extract2px(A0, B0, C0, t2, t1, pos0, pos1, p00, p01);
    extract2px(A1, B1, C1, t2, t1, pos0, pos1, p10, p11);

    float a0 = p00.x * w00, a1 = p00.y * w00, a2 = p00.z * w00;
    a0 = fmaf(p01.x, w01, a0); a1 = fmaf(p01.y, w01, a1); a2 = fmaf(p01.z, w01, a2);
    a0 = fmaf(p10.x, w10, a0); a1 = fmaf(p10.y, w10, a1); a2 = fmaf(p10.z, w10, a2);
    a0 = fmaf(p11.x, w11, a0); a1 = fmaf(p11.y, w11, a1); a2 = fmaf(p11.z, w11, a2);

    float* o = out + (size_t)(l * IMH + py) * ROWF + px * 3;
    o[0] = a0;
    o[1] = a1;
    o[2] = a2;
}

extern "C" void kernel_launch(void* const* d_in, const int* in_sizes, int n_in,
                              void* d_out, int out_size) {
    const float* x     = (const float*)d_in[0];   // (8,32,224,224,3)
    const float* noise = (const float*)d_in[1];   // (4, 766)
    const float* basis = (const float*)d_in[2];   // (4, 3, 3)
    float* out = (float*)d_out;

    smooth_matrices_kernel<<<LFRAMES, 128>>>(noise, basis);
    warp_kernel<<<dim3(IMH, LFRAMES), IMW>>>(x, out);
}